// round 2
// baseline (speedup 1.0000x reference)
#include <cuda_runtime.h>
#include <cuda_bf16.h>
#include <cstdint>

// Problem dims
#define M_ROWS 8192
#define K_DIM  4096
#define N_DIM  16384

// GEMM tiling
#define BM 128
#define BN 256
#define BK 32
#define STAGES 4
#define THREADS 256
#define ITERS (K_DIM / BK)               // 128
#define MT_TILES (M_ROWS / BM)           // 64
#define NT_TILES (N_DIM / BN)            // 64
#define GRID_BLKS (MT_TILES * NT_TILES)  // 4096

// SMEM: padded rows (32 bf16 = 64B data + 16B pad = 80B) -> conflict-free ldmatrix
#define ASTRIDE 40                       // bf16 elems per smem row
#define A_ST_BYTES (BM * ASTRIDE * 2)    // 10240
#define B_ST_BYTES (BN * ASTRIDE * 2)    // 20480
#define STAGE_BYTES (2 * A_ST_BYTES + B_ST_BYTES)   // 40960
#define SMEM_BYTES (STAGES * STAGE_BYTES)           // 163840

// ---------------- persistent scratch ----------------
__device__ __align__(256) __nv_bfloat16 g_xhi[(size_t)M_ROWS * K_DIM];
__device__ __align__(256) __nv_bfloat16 g_xlo[(size_t)M_ROWS * K_DIM];
__device__ __align__(256) __nv_bfloat16 g_w  [(size_t)N_DIM  * K_DIM];

// ---------------- helpers (arch-generic PTX only) ----------------
__device__ __forceinline__ uint32_t smem_u32(const void* p) {
    uint32_t a;
    asm("{ .reg .u64 t; cvta.to.shared.u64 t, %1; cvt.u32.u64 %0, t; }" : "=r"(a) : "l"(p));
    return a;
}
__device__ __forceinline__ void cp_async16(uint32_t dst, const void* src) {
    asm volatile("cp.async.cg.shared.global [%0], [%1], 16;" :: "r"(dst), "l"(src) : "memory");
}
__device__ __forceinline__ void cp_commit() {
    asm volatile("cp.async.commit_group;" ::: "memory");
}
__device__ __forceinline__ void cp_wait2() {
    asm volatile("cp.async.wait_group 2;" ::: "memory");
}
#define LDSM_X4(r0, r1, r2, r3, addr) \
    asm volatile("ldmatrix.sync.aligned.m8n8.x4.shared.b16 {%0,%1,%2,%3}, [%4];" \
        : "=r"(r0), "=r"(r1), "=r"(r2), "=r"(r3) : "r"(addr))

#define MMA_BF16(c, a, b0, b1) \
    asm volatile("mma.sync.aligned.m16n8k16.row.col.f32.bf16.bf16.f32 " \
        "{%0,%1,%2,%3}, {%4,%5,%6,%7}, {%8,%9}, {%0,%1,%2,%3};" \
        : "+f"((c)[0]), "+f"((c)[1]), "+f"((c)[2]), "+f"((c)[3]) \
        : "r"((a)[0]), "r"((a)[1]), "r"((a)[2]), "r"((a)[3]), "r"(b0), "r"(b1))

__device__ __forceinline__ uint32_t pack2(__nv_bfloat16 a, __nv_bfloat16 b) {
    return (uint32_t)__bfloat16_as_ushort(a) | ((uint32_t)__bfloat16_as_ushort(b) << 16);
}

// ---------------- prep: x -> (hi, lo) bf16 row-major; w -> bf16 row-major ----------------
__global__ void prep_x_kernel(const float* __restrict__ x) {
    size_t i = ((size_t)blockIdx.x * blockDim.x + threadIdx.x) * 4;
    if (i >= (size_t)M_ROWS * K_DIM) return;
    float4 v = *reinterpret_cast<const float4*>(x + i);
    __nv_bfloat16 h0 = __float2bfloat16(v.x);
    __nv_bfloat16 h1 = __float2bfloat16(v.y);
    __nv_bfloat16 h2 = __float2bfloat16(v.z);
    __nv_bfloat16 h3 = __float2bfloat16(v.w);
    __nv_bfloat16 l0 = __float2bfloat16(v.x - __bfloat162float(h0));
    __nv_bfloat16 l1 = __float2bfloat16(v.y - __bfloat162float(h1));
    __nv_bfloat16 l2 = __float2bfloat16(v.z - __bfloat162float(h2));
    __nv_bfloat16 l3 = __float2bfloat16(v.w - __bfloat162float(h3));
    *reinterpret_cast<uint2*>(&g_xhi[i]) = make_uint2(pack2(h0, h1), pack2(h2, h3));
    *reinterpret_cast<uint2*>(&g_xlo[i]) = make_uint2(pack2(l0, l1), pack2(l2, l3));
}
__global__ void prep_w_kernel(const float* __restrict__ qw) {
    size_t i = ((size_t)blockIdx.x * blockDim.x + threadIdx.x) * 4;
    if (i >= (size_t)N_DIM * K_DIM) return;
    float4 v = *reinterpret_cast<const float4*>(qw + i);
    // integer-valued in [-127,127] -> exact in bf16
    *reinterpret_cast<uint2*>(&g_w[i]) = make_uint2(
        pack2(__float2bfloat16(v.x), __float2bfloat16(v.y)),
        pack2(__float2bfloat16(v.z), __float2bfloat16(v.w)));
}

// ---------------- main GEMM ----------------
__global__ void __launch_bounds__(THREADS, 1)
gemm_kernel(const float* __restrict__ wsc, const float* __restrict__ qb,
            const float* __restrict__ bsc, float* __restrict__ out) {
    extern __shared__ __align__(128) char smem_raw[];
    const uint32_t sbase = smem_u32(smem_raw);

    const int tid  = threadIdx.x;
    const int wid  = tid >> 5;
    const int lane = tid & 31;

    // raster: groups of 8 m-tiles x 64 n-tiles  -> wave footprint ~54MB (fits L2)
    const int bid = blockIdx.x;
    const int gm8 = bid >> 9;
    const int r   = bid & 511;
    const int mt  = (gm8 << 3) + (r & 7);
    const int nt  = r >> 3;
    const size_t m0 = (size_t)mt * BM;
    const size_t n0 = (size_t)nt * BN;

    const __nv_bfloat16* gAh = g_xhi + m0 * K_DIM;
    const __nv_bfloat16* gAl = g_xlo + m0 * K_DIM;
    const __nv_bfloat16* gB  = g_w   + n0 * K_DIM;

    // per-thread cp.async geometry
    const int ar = tid >> 2;        // A row (0..63, +64 with i=1)
    const int ac = tid & 3;         // 16B chunk within 64B row

    float acc[4][8][4];
    #pragma unroll
    for (int i = 0; i < 4; i++)
        #pragma unroll
        for (int j = 0; j < 8; j++)
            #pragma unroll
            for (int q = 0; q < 4; q++) acc[i][j][q] = 0.0f;

    // ---- stage issue ----
    auto issue = [&](int it, int s) {
        const uint32_t so = sbase + (uint32_t)s * STAGE_BYTES;
        const int k0 = it * BK;
        #pragma unroll
        for (int i = 0; i < 2; i++) {
            int row = ar + i * 64;
            uint32_t dst = so + (uint32_t)row * 80 + (uint32_t)ac * 16;
            cp_async16(dst,                 gAh + (size_t)row * K_DIM + k0 + ac * 8);
            cp_async16(dst + A_ST_BYTES,    gAl + (size_t)row * K_DIM + k0 + ac * 8);
        }
        #pragma unroll
        for (int i = 0; i < 4; i++) {
            int row = ar + i * 64;
            uint32_t dst = so + 2 * A_ST_BYTES + (uint32_t)row * 80 + (uint32_t)ac * 16;
            cp_async16(dst, gB + (size_t)row * K_DIM + k0 + ac * 8);
        }
    };

    // prologue: 3 stages
    issue(0, 0); cp_commit();
    issue(1, 1); cp_commit();
    issue(2, 2); cp_commit();

    const int wm = wid & 1;          // 2 m-warps
    const int wn = wid >> 1;         // 4 n-warps

    // ldmatrix lane addressing (precompute row/col pieces)
    const int a_row_l = (lane & 15);           // within m16 tile
    const int a_col_l = (lane >> 4) * 8;       // k chunk
    const int b_row_l = ((lane >> 4) << 3) + (lane & 7);  // within n16 pair
    const int b_col_l = ((lane >> 3) & 1) * 8;            // k chunk

    for (int it = 0; it < ITERS; ++it) {
        const int s = it & 3;
        cp_wait2();
        __syncthreads();
        if (it + 3 < ITERS) issue(it + 3, (it + 3) & 3);
        cp_commit();

        const uint32_t sAh = sbase + (uint32_t)s * STAGE_BYTES;
        const uint32_t sAl = sAh + A_ST_BYTES;
        const uint32_t sB  = sAh + 2 * A_ST_BYTES;

        #pragma unroll
        for (int kk = 0; kk < BK; kk += 16) {
            uint32_t b[4][4];
            #pragma unroll
            for (int nj4 = 0; nj4 < 4; nj4++) {
                int n = wn * 64 + nj4 * 16 + b_row_l;
                int c = kk + b_col_l;
                LDSM_X4(b[nj4][0], b[nj4][1], b[nj4][2], b[nj4][3],
                        sB + ((uint32_t)n * ASTRIDE + (uint32_t)c) * 2);
            }
            uint32_t a[4][4];
            // hi pass
            #pragma unroll
            for (int mi = 0; mi < 4; mi++) {
                int mr = wm * 64 + mi * 16 + a_row_l;
                int c  = kk + a_col_l;
                LDSM_X4(a[mi][0], a[mi][1], a[mi][2], a[mi][3],
                        sAh + ((uint32_t)mr * ASTRIDE + (uint32_t)c) * 2);
            }
            #pragma unroll
            for (int mi = 0; mi < 4; mi++)
                #pragma unroll
                for (int nj4 = 0; nj4 < 4; nj4++) {
                    MMA_BF16(acc[mi][nj4 * 2 + 0], a[mi], b[nj4][0], b[nj4][1]);
                    MMA_BF16(acc[mi][nj4 * 2 + 1], a[mi], b[nj4][2], b[nj4][3]);
                }
            // lo pass (reuse B frags)
            #pragma unroll
            for (int mi = 0; mi < 4; mi++) {
                int mr = wm * 64 + mi * 16 + a_row_l;
                int c  = kk + a_col_l;
                LDSM_X4(a[mi][0], a[mi][1], a[mi][2], a[mi][3],
                        sAl + ((uint32_t)mr * ASTRIDE + (uint32_t)c) * 2);
            }
            #pragma unroll
            for (int mi = 0; mi < 4; mi++)
                #pragma unroll
                for (int nj4 = 0; nj4 < 4; nj4++) {
                    MMA_BF16(acc[mi][nj4 * 2 + 0], a[mi], b[nj4][0], b[nj4][1]);
                    MMA_BF16(acc[mi][nj4 * 2 + 1], a[mi], b[nj4][2], b[nj4][3]);
                }
        }
    }

    // ---- epilogue: y = acc/w_scale + q_bias/b_scale ----
    const float inv_ws = 1.0f / __ldg(wsc);
    const float inv_bs = 1.0f / __ldg(bsc);
    const int gid = lane >> 2;
    const int tig = lane & 3;

    #pragma unroll
    for (int nj = 0; nj < 8; nj++) {
        const size_t col = n0 + (size_t)wn * 64 + nj * 8 + tig * 2;
        float2 bv = *reinterpret_cast<const float2*>(qb + col);
        bv.x *= inv_bs; bv.y *= inv_bs;
        #pragma unroll
        for (int mi = 0; mi < 4; mi++) {
            const size_t row = m0 + (size_t)wm * 64 + mi * 16 + gid;
            float2 v0, v1;
            v0.x = acc[mi][nj][0] * inv_ws + bv.x;
            v0.y = acc[mi][nj][1] * inv_ws + bv.y;
            v1.x = acc[mi][nj][2] * inv_ws + bv.x;
            v1.y = acc[mi][nj][3] * inv_ws + bv.y;
            *reinterpret_cast<float2*>(out + row * N_DIM + col)       = v0;
            *reinterpret_cast<float2*>(out + (row + 8) * N_DIM + col) = v1;
        }
    }
}

// ---------------- launch ----------------
extern "C" void kernel_launch(void* const* d_in, const int* in_sizes, int n_in,
                              void* d_out, int out_size) {
    const float* x   = (const float*)d_in[0];
    const float* qw  = (const float*)d_in[1];
    const float* wsc = (const float*)d_in[2];
    const float* qb  = (const float*)d_in[3];
    const float* bsc = (const float*)d_in[4];
    float* out = (float*)d_out;

    {
        size_t nx = (size_t)M_ROWS * K_DIM / 4;
        prep_x_kernel<<<(unsigned)((nx + 255) / 256), 256>>>(x);
        size_t nw = (size_t)N_DIM * K_DIM / 4;
        prep_w_kernel<<<(unsigned)((nw + 255) / 256), 256>>>(qw);
    }

    static int configured = 0;
    if (!configured) {
        cudaFuncSetAttribute(gemm_kernel, cudaFuncAttributeMaxDynamicSharedMemorySize, SMEM_BYTES);
        configured = 1;
    }
    gemm_kernel<<<GRID_BLKS, THREADS, SMEM_BYTES>>>(wsc, qb, bsc, out);
}

// round 3
// speedup vs baseline: 1.6227x; 1.6227x over previous
#include <cuda_runtime.h>
#include <cuda_fp16.h>
#include <cstdint>

// Problem dims
#define M_ROWS 8192
#define K_DIM  4096
#define N_DIM  16384

// GEMM tiling
#define BM 128
#define BN 256
#define BK 32
#define STAGES 4
#define THREADS 256
#define ITERS (K_DIM / BK)               // 128
#define MT_TILES (M_ROWS / BM)           // 64
#define NT_TILES (N_DIM / BN)            // 64
#define GRID_BLKS (MT_TILES * NT_TILES)  // 4096

// SMEM: padded rows (32 fp16 = 64B data + 16B pad = 80B) -> conflict-light ldmatrix
#define ASTRIDE 40                       // fp16 elems per smem row
#define A_ST_BYTES (BM * ASTRIDE * 2)    // 10240
#define B_ST_BYTES (BN * ASTRIDE * 2)    // 20480
#define STAGE_BYTES (A_ST_BYTES + B_ST_BYTES)       // 30720
#define SMEM_BYTES (STAGES * STAGE_BYTES)           // 122880

// ---------------- persistent scratch ----------------
__device__ __align__(256) __half g_xh[(size_t)M_ROWS * K_DIM];
__device__ __align__(256) __half g_w [(size_t)N_DIM  * K_DIM];

// ---------------- helpers (arch-generic PTX only) ----------------
__device__ __forceinline__ uint32_t smem_u32(const void* p) {
    uint32_t a;
    asm("{ .reg .u64 t; cvta.to.shared.u64 t, %1; cvt.u32.u64 %0, t; }" : "=r"(a) : "l"(p));
    return a;
}
__device__ __forceinline__ void cp_async16(uint32_t dst, const void* src) {
    asm volatile("cp.async.cg.shared.global [%0], [%1], 16;" :: "r"(dst), "l"(src) : "memory");
}
__device__ __forceinline__ void cp_commit() {
    asm volatile("cp.async.commit_group;" ::: "memory");
}
__device__ __forceinline__ void cp_wait2() {
    asm volatile("cp.async.wait_group 2;" ::: "memory");
}
#define LDSM_X4(r0, r1, r2, r3, addr) \
    asm volatile("ldmatrix.sync.aligned.m8n8.x4.shared.b16 {%0,%1,%2,%3}, [%4];" \
        : "=r"(r0), "=r"(r1), "=r"(r2), "=r"(r3) : "r"(addr))

#define MMA_F16(c, a, b0, b1) \
    asm volatile("mma.sync.aligned.m16n8k16.row.col.f32.f16.f16.f32 " \
        "{%0,%1,%2,%3}, {%4,%5,%6,%7}, {%8,%9}, {%0,%1,%2,%3};" \
        : "+f"((c)[0]), "+f"((c)[1]), "+f"((c)[2]), "+f"((c)[3]) \
        : "r"((a)[0]), "r"((a)[1]), "r"((a)[2]), "r"((a)[3]), "r"(b0), "r"(b1))

__device__ __forceinline__ uint32_t pack2h(__half a, __half b) {
    return (uint32_t)__half_as_ushort(a) | ((uint32_t)__half_as_ushort(b) << 16);
}

// ---------------- prep: x -> fp16 row-major; w -> fp16 row-major (exact ints) ----------------
__global__ void prep_x_kernel(const float* __restrict__ x) {
    size_t i = ((size_t)blockIdx.x * blockDim.x + threadIdx.x) * 4;
    if (i >= (size_t)M_ROWS * K_DIM) return;
    float4 v = *reinterpret_cast<const float4*>(x + i);
    *reinterpret_cast<uint2*>(&g_xh[i]) = make_uint2(
        pack2h(__float2half_rn(v.x), __float2half_rn(v.y)),
        pack2h(__float2half_rn(v.z), __float2half_rn(v.w)));
}
__global__ void prep_w_kernel(const float* __restrict__ qw) {
    size_t i = ((size_t)blockIdx.x * blockDim.x + threadIdx.x) * 4;
    if (i >= (size_t)N_DIM * K_DIM) return;
    float4 v = *reinterpret_cast<const float4*>(qw + i);
    // integer-valued in [-127,127] -> exact in fp16
    *reinterpret_cast<uint2*>(&g_w[i]) = make_uint2(
        pack2h(__float2half_rn(v.x), __float2half_rn(v.y)),
        pack2h(__float2half_rn(v.z), __float2half_rn(v.w)));
}

// ---------------- main GEMM (single fp16 pass) ----------------
__global__ void __launch_bounds__(THREADS, 1)
gemm_kernel(const float* __restrict__ wsc, const float* __restrict__ qb,
            const float* __restrict__ bsc, float* __restrict__ out) {
    extern __shared__ __align__(128) char smem_raw[];
    const uint32_t sbase = smem_u32(smem_raw);

    const int tid  = threadIdx.x;
    const int wid  = tid >> 5;
    const int lane = tid & 31;

    // raster: groups of 8 m-tiles x 64 n-tiles -> wave footprint fits L2
    const int bid = blockIdx.x;
    const int gm8 = bid >> 9;
    const int r   = bid & 511;
    const int mt  = (gm8 << 3) + (r & 7);
    const int nt  = r >> 3;
    const size_t m0 = (size_t)mt * BM;
    const size_t n0 = (size_t)nt * BN;

    const __half* gA = g_xh + m0 * K_DIM;
    const __half* gB = g_w  + n0 * K_DIM;

    // per-thread cp.async geometry
    const int ar = tid >> 2;        // row (0..63, +64 per i)
    const int ac = tid & 3;         // 16B chunk within 64B row

    float acc[4][8][4];
    #pragma unroll
    for (int i = 0; i < 4; i++)
        #pragma unroll
        for (int j = 0; j < 8; j++)
            #pragma unroll
            for (int q = 0; q < 4; q++) acc[i][j][q] = 0.0f;

    auto issue = [&](int it, int s) {
        const uint32_t so = sbase + (uint32_t)s * STAGE_BYTES;
        const int k0 = it * BK;
        #pragma unroll
        for (int i = 0; i < 2; i++) {
            int row = ar + i * 64;
            cp_async16(so + (uint32_t)row * 80 + (uint32_t)ac * 16,
                       gA + (size_t)row * K_DIM + k0 + ac * 8);
        }
        #pragma unroll
        for (int i = 0; i < 4; i++) {
            int row = ar + i * 64;
            cp_async16(so + A_ST_BYTES + (uint32_t)row * 80 + (uint32_t)ac * 16,
                       gB + (size_t)row * K_DIM + k0 + ac * 8);
        }
    };

    // prologue: 3 stages in flight
    issue(0, 0); cp_commit();
    issue(1, 1); cp_commit();
    issue(2, 2); cp_commit();

    const int wm = wid & 1;          // 2 m-warps
    const int wn = wid >> 1;         // 4 n-warps

    const int a_row_l = (lane & 15);
    const int a_col_l = (lane >> 4) * 8;
    const int b_row_l = ((lane >> 4) << 3) + (lane & 7);
    const int b_col_l = ((lane >> 3) & 1) * 8;

    for (int it = 0; it < ITERS; ++it) {
        const int s = it & 3;
        cp_wait2();
        __syncthreads();
        if (it + 3 < ITERS) issue(it + 3, (it + 3) & 3);
        cp_commit();

        const uint32_t sA = sbase + (uint32_t)s * STAGE_BYTES;
        const uint32_t sB = sA + A_ST_BYTES;

        #pragma unroll
        for (int kk = 0; kk < BK; kk += 16) {
            uint32_t b[4][4];
            #pragma unroll
            for (int nj4 = 0; nj4 < 4; nj4++) {
                int n = wn * 64 + nj4 * 16 + b_row_l;
                int c = kk + b_col_l;
                LDSM_X4(b[nj4][0], b[nj4][1], b[nj4][2], b[nj4][3],
                        sB + ((uint32_t)n * ASTRIDE + (uint32_t)c) * 2);
            }
            uint32_t a[4][4];
            #pragma unroll
            for (int mi = 0; mi < 4; mi++) {
                int mr = wm * 64 + mi * 16 + a_row_l;
                int c  = kk + a_col_l;
                LDSM_X4(a[mi][0], a[mi][1], a[mi][2], a[mi][3],
                        sA + ((uint32_t)mr * ASTRIDE + (uint32_t)c) * 2);
            }
            #pragma unroll
            for (int mi = 0; mi < 4; mi++)
                #pragma unroll
                for (int nj4 = 0; nj4 < 4; nj4++) {
                    MMA_F16(acc[mi][nj4 * 2 + 0], a[mi], b[nj4][0], b[nj4][1]);
                    MMA_F16(acc[mi][nj4 * 2 + 1], a[mi], b[nj4][2], b[nj4][3]);
                }
        }
    }

    // ---- epilogue: y = acc/w_scale + q_bias/b_scale ----
    const float inv_ws = 1.0f / __ldg(wsc);
    const float inv_bs = 1.0f / __ldg(bsc);
    const int gid = lane >> 2;
    const int tig = lane & 3;

    #pragma unroll
    for (int nj = 0; nj < 8; nj++) {
        const size_t col = n0 + (size_t)wn * 64 + nj * 8 + tig * 2;
        float2 bv = *reinterpret_cast<const float2*>(qb + col);
        bv.x *= inv_bs; bv.y *= inv_bs;
        #pragma unroll
        for (int mi = 0; mi < 4; mi++) {
            const size_t row = m0 + (size_t)wm * 64 + mi * 16 + gid;
            float2 v0, v1;
            v0.x = acc[mi][nj][0] * inv_ws + bv.x;
            v0.y = acc[mi][nj][1] * inv_ws + bv.y;
            v1.x = acc[mi][nj][2] * inv_ws + bv.x;
            v1.y = acc[mi][nj][3] * inv_ws + bv.y;
            *reinterpret_cast<float2*>(out + row * N_DIM + col)       = v0;
            *reinterpret_cast<float2*>(out + (row + 8) * N_DIM + col) = v1;
        }
    }
}

// ---------------- launch ----------------
extern "C" void kernel_launch(void* const* d_in, const int* in_sizes, int n_in,
                              void* d_out, int out_size) {
    const float* x   = (const float*)d_in[0];
    const float* qw  = (const float*)d_in[1];
    const float* wsc = (const float*)d_in[2];
    const float* qb  = (const float*)d_in[3];
    const float* bsc = (const float*)d_in[4];
    float* out = (float*)d_out;

    {
        size_t nx = (size_t)M_ROWS * K_DIM / 4;
        prep_x_kernel<<<(unsigned)((nx + 255) / 256), 256>>>(x);
        size_t nw = (size_t)N_DIM * K_DIM / 4;
        prep_w_kernel<<<(unsigned)((nw + 255) / 256), 256>>>(qw);
    }

    static int configured = 0;
    if (!configured) {
        cudaFuncSetAttribute(gemm_kernel, cudaFuncAttributeMaxDynamicSharedMemorySize, SMEM_BYTES);
        configured = 1;
    }
    gemm_kernel<<<GRID_BLKS, THREADS, SMEM_BYTES>>>(wsc, qb, bsc, out);
}

// round 4
// speedup vs baseline: 1.9233x; 1.1852x over previous
#include <cuda_runtime.h>
#include <cuda_fp16.h>
#include <cstdint>

// Problem dims
#define M_ROWS 8192
#define K_DIM  4096
#define N_DIM  16384

// GEMM tiling
#define BM 128
#define BN 256
#define BK 64
#define STAGES 4
#define THREADS 256
#define ITERS (K_DIM / BK)               // 64
#define MT_TILES (M_ROWS / BM)           // 64
#define NT_TILES (N_DIM / BN)            // 64
#define GRID_BLKS (MT_TILES * NT_TILES)  // 4096

// SMEM: rows of 64 fp16 = 128B data + 16B pad = 144B -> conflict-free ldmatrix
#define ASTRIDE 72                       // fp16 elems per smem row
#define ROWB 144
#define A_ST_BYTES (BM * ROWB)           // 18432
#define B_ST_BYTES (BN * ROWB)           // 36864
#define STAGE_BYTES (A_ST_BYTES + B_ST_BYTES)       // 55296
#define SMEM_BYTES (STAGES * STAGE_BYTES)           // 221184

// ---------------- persistent scratch ----------------
__device__ __align__(256) __half g_xh[(size_t)M_ROWS * K_DIM];
__device__ __align__(256) __half g_w [(size_t)N_DIM  * K_DIM];

// ---------------- helpers (arch-generic PTX only) ----------------
__device__ __forceinline__ uint32_t smem_u32(const void* p) {
    uint32_t a;
    asm("{ .reg .u64 t; cvta.to.shared.u64 t, %1; cvt.u32.u64 %0, t; }" : "=r"(a) : "l"(p));
    return a;
}
__device__ __forceinline__ void cp_async16(uint32_t dst, const void* src) {
    asm volatile("cp.async.cg.shared.global [%0], [%1], 16;" :: "r"(dst), "l"(src) : "memory");
}
__device__ __forceinline__ void cp_commit() {
    asm volatile("cp.async.commit_group;" ::: "memory");
}
__device__ __forceinline__ void cp_wait2() {
    asm volatile("cp.async.wait_group 2;" ::: "memory");
}
#define LDSM_X4(r0, r1, r2, r3, addr) \
    asm volatile("ldmatrix.sync.aligned.m8n8.x4.shared.b16 {%0,%1,%2,%3}, [%4];" \
        : "=r"(r0), "=r"(r1), "=r"(r2), "=r"(r3) : "r"(addr))

#define MMA_F16(c, a, b0, b1) \
    asm volatile("mma.sync.aligned.m16n8k16.row.col.f32.f16.f16.f32 " \
        "{%0,%1,%2,%3}, {%4,%5,%6,%7}, {%8,%9}, {%0,%1,%2,%3};" \
        : "+f"((c)[0]), "+f"((c)[1]), "+f"((c)[2]), "+f"((c)[3]) \
        : "r"((a)[0]), "r"((a)[1]), "r"((a)[2]), "r"((a)[3]), "r"(b0), "r"(b1))

__device__ __forceinline__ uint32_t pack2h(__half a, __half b) {
    return (uint32_t)__half_as_ushort(a) | ((uint32_t)__half_as_ushort(b) << 16);
}

// ---------------- prep ----------------
__global__ void prep_x_kernel(const float* __restrict__ x) {
    size_t i = ((size_t)blockIdx.x * blockDim.x + threadIdx.x) * 4;
    if (i >= (size_t)M_ROWS * K_DIM) return;
    float4 v = *reinterpret_cast<const float4*>(x + i);
    *reinterpret_cast<uint2*>(&g_xh[i]) = make_uint2(
        pack2h(__float2half_rn(v.x), __float2half_rn(v.y)),
        pack2h(__float2half_rn(v.z), __float2half_rn(v.w)));
}
__global__ void prep_w_kernel(const float* __restrict__ qw) {
    size_t i = ((size_t)blockIdx.x * blockDim.x + threadIdx.x) * 4;
    if (i >= (size_t)N_DIM * K_DIM) return;
    float4 v = *reinterpret_cast<const float4*>(qw + i);
    // integer-valued in [-127,127] -> exact in fp16
    *reinterpret_cast<uint2*>(&g_w[i]) = make_uint2(
        pack2h(__float2half_rn(v.x), __float2half_rn(v.y)),
        pack2h(__float2half_rn(v.z), __float2half_rn(v.w)));
}

// ---------------- main GEMM ----------------
__global__ void __launch_bounds__(THREADS, 1)
gemm_kernel(const float* __restrict__ wsc, const float* __restrict__ qb,
            const float* __restrict__ bsc, float* __restrict__ out) {
    extern __shared__ __align__(128) char smem_raw[];
    const uint32_t sbase = smem_u32(smem_raw);

    const int tid  = threadIdx.x;
    const int wid  = tid >> 5;
    const int lane = tid & 31;

    // raster: groups of 8 m-tiles x 64 n-tiles -> wave footprint fits L2
    const int bid = blockIdx.x;
    const int gm8 = bid >> 9;
    const int r   = bid & 511;
    const int mt  = (gm8 << 3) + (r & 7);
    const int nt  = r >> 3;
    const size_t m0 = (size_t)mt * BM;
    const size_t n0 = (size_t)nt * BN;

    const __half* gA = g_xh + m0 * K_DIM;
    const __half* gB = g_w  + n0 * K_DIM;

    // cp.async geometry: rows of 128B = 8 x 16B chunks
    const int ar = tid >> 3;        // row 0..31 (+32 per i)
    const int ac = tid & 7;         // 16B chunk

    float acc[4][8][4];
    #pragma unroll
    for (int i = 0; i < 4; i++)
        #pragma unroll
        for (int j = 0; j < 8; j++)
            #pragma unroll
            for (int q = 0; q < 4; q++) acc[i][j][q] = 0.0f;

    auto issue = [&](int it, int s) {
        const uint32_t so = sbase + (uint32_t)s * STAGE_BYTES;
        const int k0 = it * BK;
        #pragma unroll
        for (int i = 0; i < 4; i++) {
            int row = ar + i * 32;
            cp_async16(so + (uint32_t)row * ROWB + (uint32_t)ac * 16,
                       gA + (size_t)row * K_DIM + k0 + ac * 8);
        }
        #pragma unroll
        for (int i = 0; i < 8; i++) {
            int row = ar + i * 32;
            cp_async16(so + A_ST_BYTES + (uint32_t)row * ROWB + (uint32_t)ac * 16,
                       gB + (size_t)row * K_DIM + k0 + ac * 8);
        }
    };

    // prologue: 3 stages in flight
    issue(0, 0); cp_commit();
    issue(1, 1); cp_commit();
    issue(2, 2); cp_commit();

    const int wm = wid & 1;          // 2 m-warps
    const int wn = wid >> 1;         // 4 n-warps

    const int a_row_l = (lane & 15);
    const int a_col_l = (lane >> 4) * 8;
    const int b_row_l = ((lane >> 4) << 3) + (lane & 7);
    const int b_col_l = ((lane >> 3) & 1) * 8;

    for (int it = 0; it < ITERS; ++it) {
        const int s = it & 3;
        cp_wait2();
        __syncthreads();
        if (it + 3 < ITERS) issue(it + 3, (it + 3) & 3);
        cp_commit();

        const uint32_t sA = sbase + (uint32_t)s * STAGE_BYTES;
        const uint32_t sB = sA + A_ST_BYTES;

        #pragma unroll
        for (int kk = 0; kk < BK; kk += 16) {
            uint32_t b[4][4];
            #pragma unroll
            for (int nj4 = 0; nj4 < 4; nj4++) {
                int n = wn * 64 + nj4 * 16 + b_row_l;
                int c = kk + b_col_l;
                LDSM_X4(b[nj4][0], b[nj4][1], b[nj4][2], b[nj4][3],
                        sB + ((uint32_t)n * ASTRIDE + (uint32_t)c) * 2);
            }
            uint32_t a[4][4];
            #pragma unroll
            for (int mi = 0; mi < 4; mi++) {
                int mr = wm * 64 + mi * 16 + a_row_l;
                int c  = kk + a_col_l;
                LDSM_X4(a[mi][0], a[mi][1], a[mi][2], a[mi][3],
                        sA + ((uint32_t)mr * ASTRIDE + (uint32_t)c) * 2);
            }
            #pragma unroll
            for (int mi = 0; mi < 4; mi++)
                #pragma unroll
                for (int nj4 = 0; nj4 < 4; nj4++) {
                    MMA_F16(acc[mi][nj4 * 2 + 0], a[mi], b[nj4][0], b[nj4][1]);
                    MMA_F16(acc[mi][nj4 * 2 + 1], a[mi], b[nj4][2], b[nj4][3]);
                }
        }
    }

    // ---- epilogue: y = acc/w_scale + q_bias/b_scale ----
    const float inv_ws = 1.0f / __ldg(wsc);
    const float inv_bs = 1.0f / __ldg(bsc);
    const int gid = lane >> 2;
    const int tig = lane & 3;

    #pragma unroll
    for (int nj = 0; nj < 8; nj++) {
        const size_t col = n0 + (size_t)wn * 64 + nj * 8 + tig * 2;
        float2 bv = *reinterpret_cast<const float2*>(qb + col);
        bv.x *= inv_bs; bv.y *= inv_bs;
        #pragma unroll
        for (int mi = 0; mi < 4; mi++) {
            const size_t row = m0 + (size_t)wm * 64 + mi * 16 + gid;
            float2 v0, v1;
            v0.x = acc[mi][nj][0] * inv_ws + bv.x;
            v0.y = acc[mi][nj][1] * inv_ws + bv.y;
            v1.x = acc[mi][nj][2] * inv_ws + bv.x;
            v1.y = acc[mi][nj][3] * inv_ws + bv.y;
            *reinterpret_cast<float2*>(out + row * N_DIM + col)       = v0;
            *reinterpret_cast<float2*>(out + (row + 8) * N_DIM + col) = v1;
        }
    }
}

// ---------------- launch ----------------
extern "C" void kernel_launch(void* const* d_in, const int* in_sizes, int n_in,
                              void* d_out, int out_size) {
    const float* x   = (const float*)d_in[0];
    const float* qw  = (const float*)d_in[1];
    const float* wsc = (const float*)d_in[2];
    const float* qb  = (const float*)d_in[3];
    const float* bsc = (const float*)d_in[4];
    float* out = (float*)d_out;

    {
        size_t nx = (size_t)M_ROWS * K_DIM / 4;
        prep_x_kernel<<<(unsigned)((nx + 255) / 256), 256>>>(x);
        size_t nw = (size_t)N_DIM * K_DIM / 4;
        prep_w_kernel<<<(unsigned)((nw + 255) / 256), 256>>>(qw);
    }

    static int configured = 0;
    if (!configured) {
        cudaFuncSetAttribute(gemm_kernel, cudaFuncAttributeMaxDynamicSharedMemorySize, SMEM_BYTES);
        configured = 1;
    }
    gemm_kernel<<<GRID_BLKS, THREADS, SMEM_BYTES>>>(wsc, qb, bsc, out);
}

// round 5
// speedup vs baseline: 2.0165x; 1.0485x over previous
#include <cuda_runtime.h>
#include <cuda_fp16.h>
#include <cstdint>

// Problem dims
#define M_ROWS 8192
#define K_DIM  4096
#define N_DIM  16384

// GEMM tiling
#define BM 128
#define BN 256
#define BK 64
#define STAGES 4
#define THREADS 512
#define ITERS (K_DIM / BK)               // 64
#define MT_TILES (M_ROWS / BM)           // 64
#define NT_TILES (N_DIM / BN)            // 64
#define GRID_BLKS (MT_TILES * NT_TILES)  // 4096

// SMEM: rows of 64 fp16 = 128B data + 16B pad = 144B -> conflict-free ldmatrix
#define ASTRIDE 72                       // fp16 elems per smem row
#define ROWB 144
#define A_ST_BYTES (BM * ROWB)           // 18432
#define B_ST_BYTES (BN * ROWB)           // 36864
#define STAGE_BYTES (A_ST_BYTES + B_ST_BYTES)       // 55296
#define SMEM_BYTES (STAGES * STAGE_BYTES)           // 221184

// ---------------- persistent scratch ----------------
__device__ __align__(256) __half g_xh[(size_t)M_ROWS * K_DIM];
__device__ __align__(256) __half g_w [(size_t)N_DIM  * K_DIM];

// ---------------- helpers (arch-generic PTX only) ----------------
__device__ __forceinline__ uint32_t smem_u32(const void* p) {
    uint32_t a;
    asm("{ .reg .u64 t; cvta.to.shared.u64 t, %1; cvt.u32.u64 %0, t; }" : "=r"(a) : "l"(p));
    return a;
}
__device__ __forceinline__ void cp_async16(uint32_t dst, const void* src) {
    asm volatile("cp.async.cg.shared.global [%0], [%1], 16;" :: "r"(dst), "l"(src) : "memory");
}
__device__ __forceinline__ void cp_commit() {
    asm volatile("cp.async.commit_group;" ::: "memory");
}
__device__ __forceinline__ void cp_wait2() {
    asm volatile("cp.async.wait_group 2;" ::: "memory");
}
#define LDSM_X4(r0, r1, r2, r3, addr) \
    asm volatile("ldmatrix.sync.aligned.m8n8.x4.shared.b16 {%0,%1,%2,%3}, [%4];" \
        : "=r"(r0), "=r"(r1), "=r"(r2), "=r"(r3) : "r"(addr))

#define MMA_F16(c, a, b0, b1) \
    asm volatile("mma.sync.aligned.m16n8k16.row.col.f32.f16.f16.f32 " \
        "{%0,%1,%2,%3}, {%4,%5,%6,%7}, {%8,%9}, {%0,%1,%2,%3};" \
        : "+f"((c)[0]), "+f"((c)[1]), "+f"((c)[2]), "+f"((c)[3]) \
        : "r"((a)[0]), "r"((a)[1]), "r"((a)[2]), "r"((a)[3]), "r"(b0), "r"(b1))

__device__ __forceinline__ uint32_t pack2h(__half a, __half b) {
    return (uint32_t)__half_as_ushort(a) | ((uint32_t)__half_as_ushort(b) << 16);
}

// ---------------- prep ----------------
__global__ void prep_x_kernel(const float* __restrict__ x) {
    size_t i = ((size_t)blockIdx.x * blockDim.x + threadIdx.x) * 4;
    if (i >= (size_t)M_ROWS * K_DIM) return;
    float4 v = *reinterpret_cast<const float4*>(x + i);
    *reinterpret_cast<uint2*>(&g_xh[i]) = make_uint2(
        pack2h(__float2half_rn(v.x), __float2half_rn(v.y)),
        pack2h(__float2half_rn(v.z), __float2half_rn(v.w)));
}
__global__ void prep_w_kernel(const float* __restrict__ qw) {
    size_t i = ((size_t)blockIdx.x * blockDim.x + threadIdx.x) * 4;
    if (i >= (size_t)N_DIM * K_DIM) return;
    float4 v = *reinterpret_cast<const float4*>(qw + i);
    // integer-valued in [-127,127] -> exact in fp16
    *reinterpret_cast<uint2*>(&g_w[i]) = make_uint2(
        pack2h(__float2half_rn(v.x), __float2half_rn(v.y)),
        pack2h(__float2half_rn(v.z), __float2half_rn(v.w)));
}

// ---------------- main GEMM: 16 warps, warp tile 32x64 ----------------
__global__ void __launch_bounds__(THREADS, 1)
gemm_kernel(const float* __restrict__ wsc, const float* __restrict__ qb,
            const float* __restrict__ bsc, float* __restrict__ out) {
    extern __shared__ __align__(128) char smem_raw[];
    const uint32_t sbase = smem_u32(smem_raw);

    const int tid  = threadIdx.x;
    const int wid  = tid >> 5;
    const int lane = tid & 31;

    // raster: groups of 8 m-tiles x 64 n-tiles -> wave footprint fits L2
    const int bid = blockIdx.x;
    const int gm8 = bid >> 9;
    const int r   = bid & 511;
    const int mt  = (gm8 << 3) + (r & 7);
    const int nt  = r >> 3;
    const size_t m0 = (size_t)mt * BM;
    const size_t n0 = (size_t)nt * BN;

    const __half* gA = g_xh + m0 * K_DIM;
    const __half* gB = g_w  + n0 * K_DIM;

    // cp.async geometry: rows of 128B = 8 x 16B chunks; 512 threads -> 64 rows/pass
    const int ar = tid >> 3;        // row 0..63
    const int ac = tid & 7;         // 16B chunk

    float acc[2][8][4];
    #pragma unroll
    for (int i = 0; i < 2; i++)
        #pragma unroll
        for (int j = 0; j < 8; j++)
            #pragma unroll
            for (int q = 0; q < 4; q++) acc[i][j][q] = 0.0f;

    auto issue = [&](int it, int s) {
        const uint32_t so = sbase + (uint32_t)s * STAGE_BYTES;
        const int k0 = it * BK;
        #pragma unroll
        for (int i = 0; i < 2; i++) {
            int row = ar + i * 64;
            cp_async16(so + (uint32_t)row * ROWB + (uint32_t)ac * 16,
                       gA + (size_t)row * K_DIM + k0 + ac * 8);
        }
        #pragma unroll
        for (int i = 0; i < 4; i++) {
            int row = ar + i * 64;
            cp_async16(so + A_ST_BYTES + (uint32_t)row * ROWB + (uint32_t)ac * 16,
                       gB + (size_t)row * K_DIM + k0 + ac * 8);
        }
    };

    // prologue: 3 stages in flight
    issue(0, 0); cp_commit();
    issue(1, 1); cp_commit();
    issue(2, 2); cp_commit();

    const int wm = wid & 3;          // 4 m-warps (32 rows each)
    const int wn = wid >> 2;         // 4 n-warps (64 cols each)

    const int a_row_l = (lane & 15);
    const int a_col_l = (lane >> 4) * 8;
    const int b_row_l = ((lane >> 4) << 3) + (lane & 7);
    const int b_col_l = ((lane >> 3) & 1) * 8;

    for (int it = 0; it < ITERS; ++it) {
        const int s = it & 3;
        cp_wait2();
        __syncthreads();
        if (it + 3 < ITERS) issue(it + 3, (it + 3) & 3);
        cp_commit();

        const uint32_t sA = sbase + (uint32_t)s * STAGE_BYTES;
        const uint32_t sB = sA + A_ST_BYTES;

        #pragma unroll
        for (int kk = 0; kk < BK; kk += 16) {
            uint32_t b[4][4];
            #pragma unroll
            for (int nj4 = 0; nj4 < 4; nj4++) {
                int n = wn * 64 + nj4 * 16 + b_row_l;
                int c = kk + b_col_l;
                LDSM_X4(b[nj4][0], b[nj4][1], b[nj4][2], b[nj4][3],
                        sB + ((uint32_t)n * ASTRIDE + (uint32_t)c) * 2);
            }
            uint32_t a[2][4];
            #pragma unroll
            for (int mi = 0; mi < 2; mi++) {
                int mr = wm * 32 + mi * 16 + a_row_l;
                int c  = kk + a_col_l;
                LDSM_X4(a[mi][0], a[mi][1], a[mi][2], a[mi][3],
                        sA + ((uint32_t)mr * ASTRIDE + (uint32_t)c) * 2);
            }
            #pragma unroll
            for (int mi = 0; mi < 2; mi++)
                #pragma unroll
                for (int nj4 = 0; nj4 < 4; nj4++) {
                    MMA_F16(acc[mi][nj4 * 2 + 0], a[mi], b[nj4][0], b[nj4][1]);
                    MMA_F16(acc[mi][nj4 * 2 + 1], a[mi], b[nj4][2], b[nj4][3]);
                }
        }
    }

    // ---- epilogue: y = acc/w_scale + q_bias/b_scale ----
    const float inv_ws = 1.0f / __ldg(wsc);
    const float inv_bs = 1.0f / __ldg(bsc);
    const int gid = lane >> 2;
    const int tig = lane & 3;

    #pragma unroll
    for (int nj = 0; nj < 8; nj++) {
        const size_t col = n0 + (size_t)wn * 64 + nj * 8 + tig * 2;
        float2 bv = *reinterpret_cast<const float2*>(qb + col);
        bv.x *= inv_bs; bv.y *= inv_bs;
        #pragma unroll
        for (int mi = 0; mi < 2; mi++) {
            const size_t row = m0 + (size_t)wm * 32 + mi * 16 + gid;
            float2 v0, v1;
            v0.x = acc[mi][nj][0] * inv_ws + bv.x;
            v0.y = acc[mi][nj][1] * inv_ws + bv.y;
            v1.x = acc[mi][nj][2] * inv_ws + bv.x;
            v1.y = acc[mi][nj][3] * inv_ws + bv.y;
            *reinterpret_cast<float2*>(out + row * N_DIM + col)       = v0;
            *reinterpret_cast<float2*>(out + (row + 8) * N_DIM + col) = v1;
        }
    }
}

// ---------------- launch ----------------
extern "C" void kernel_launch(void* const* d_in, const int* in_sizes, int n_in,
                              void* d_out, int out_size) {
    const float* x   = (const float*)d_in[0];
    const float* qw  = (const float*)d_in[1];
    const float* wsc = (const float*)d_in[2];
    const float* qb  = (const float*)d_in[3];
    const float* bsc = (const float*)d_in[4];
    float* out = (float*)d_out;

    {
        size_t nx = (size_t)M_ROWS * K_DIM / 4;
        prep_x_kernel<<<(unsigned)((nx + 255) / 256), 256>>>(x);
        size_t nw = (size_t)N_DIM * K_DIM / 4;
        prep_w_kernel<<<(unsigned)((nw + 255) / 256), 256>>>(qw);
    }

    static int configured = 0;
    if (!configured) {
        cudaFuncSetAttribute(gemm_kernel, cudaFuncAttributeMaxDynamicSharedMemorySize, SMEM_BYTES);
        configured = 1;
    }
    gemm_kernel<<<GRID_BLKS, THREADS, SMEM_BYTES>>>(wsc, qb, bsc, out);
}